// round 8
// baseline (speedup 1.0000x reference)
#include <cuda_runtime.h>
#include <cuda_bf16.h>
#include <cstdint>

// Problem constants
#define SSP 32768           // H*W*D
#define NB 4
#define NPART 4096          // gemm partials: 1024 CTAs * 4 n-warp-groups

// Scratch (no allocations allowed)
__device__ __align__(16) __nv_bfloat16 g_acth[NB * 256 * SSP];  // act hi: [b][k=256][s], 64MB
__device__ __align__(16) __nv_bfloat16 g_actl[NB * 256 * SSP];  // act lo, 64MB
__device__ __align__(16) __nv_bfloat16 g_wbh[128 * 256];        // W hi, row-major [o][k]
__device__ __align__(16) __nv_bfloat16 g_wbl[128 * 256];        // W lo, row-major [o][k]
__device__ float g_part[2 * NPART * 128];
__device__ float g_part2[2 * 64 * 128];
__device__ float g_scale[128];
__device__ float g_shift[128];

// Single dynamic-SMEM symbol shared by all kernels.
extern __shared__ char dyn_smem[];

// ---------------------------------------------------------------------------
// PTX helpers (sm_80+; valid under plain sm_100 target)
// ---------------------------------------------------------------------------
__device__ __forceinline__ uint32_t smem_u32(const void* p) {
    uint32_t a;
    asm("{ .reg .u64 t; cvta.to.shared.u64 t, %1; cvt.u32.u64 %0, t; }" : "=r"(a) : "l"(p));
    return a;
}
__device__ __forceinline__ void cpasync16(uint32_t sa, const void* ga) {
    asm volatile("cp.async.cg.shared.global [%0], [%1], 16;" :: "r"(sa), "l"(ga) : "memory");
}
#define CP_COMMIT() asm volatile("cp.async.commit_group;" ::: "memory")
__device__ __forceinline__ void ldsm4(uint32_t addr, uint32_t* r) {
    asm volatile("ldmatrix.sync.aligned.m8n8.x4.shared.b16 {%0,%1,%2,%3}, [%4];"
                 : "=r"(r[0]), "=r"(r[1]), "=r"(r[2]), "=r"(r[3]) : "r"(addr));
}
__device__ __forceinline__ void ldsm4t(uint32_t addr, uint32_t* r) {
    asm volatile("ldmatrix.sync.aligned.m8n8.x4.trans.shared.b16 {%0,%1,%2,%3}, [%4];"
                 : "=r"(r[0]), "=r"(r[1]), "=r"(r[2]), "=r"(r[3]) : "r"(addr));
}
__device__ __forceinline__ void mma_bf16(float* d, const uint32_t* a, uint32_t b0, uint32_t b1) {
    asm volatile("mma.sync.aligned.m16n8k16.row.col.f32.bf16.bf16.f32 "
                 "{%0,%1,%2,%3}, {%4,%5,%6,%7}, {%8,%9}, {%0,%1,%2,%3};"
                 : "+f"(d[0]), "+f"(d[1]), "+f"(d[2]), "+f"(d[3])
                 : "r"(a[0]), "r"(a[1]), "r"(a[2]), "r"(a[3]), "r"(b0), "r"(b1));
}

// ---------------------------------------------------------------------------
// Kernel 1: x_j + fp32->bf16 hi/lo conversion of BOTH act halves.
// One CTA per (b,c) slice. x_j = max(0, x - exclusive same-parity min / axis).
// ---------------------------------------------------------------------------
__global__ __launch_bounds__(1024) void xj_kernel(const float* __restrict__ x) {
    float* s  = (float*)dyn_smem;
    float* st = (float*)dyn_smem + 32768;
    const int tid = threadIdx.x;
    const int bidx = blockIdx.x;                 // b*128 + c
    const int b = bidx >> 7, c = bidx & 127;
    const size_t base = (size_t)bidx * SSP;
    const size_t xoff = ((size_t)b * 256 + c) * SSP;          // act k = c
    const size_t joff = ((size_t)b * 256 + 128 + c) * SSP;    // act k = 128+c

    for (int i = tid; i < SSP; i += 1024) {
        const float v = x[base + i];
        s[i] = v;
        const __nv_bfloat16 h = __float2bfloat16(v);
        g_acth[xoff + i] = h;
        g_actl[xoff + i] = __float2bfloat16(v - __bfloat162float(h));
    }
    __syncthreads();

    for (int t = tid; t < 2048; t += 1024) {
        const int l = t >> 1, p = t & 1;
        {   // D axis
            const float* bp = s + l * 32 + p;
            float m1 = 1e30f, m2 = 1e30f; int i1 = -1;
            #pragma unroll
            for (int kk = 0; kk < 16; ++kk) {
                float v = bp[kk * 2];
                if (v < m1) { m2 = m1; m1 = v; i1 = p + 2 * kk; } else if (v < m2) m2 = v;
            }
            st[t] = m1; st[2048 + t] = m2; st[4096 + t] = (float)i1;
        }
        {   // W axis
            const float* bp = s + (l >> 5) * 1024 + (l & 31) + p * 32;
            float m1 = 1e30f, m2 = 1e30f; int i1 = -1;
            #pragma unroll
            for (int kk = 0; kk < 16; ++kk) {
                float v = bp[kk * 64];
                if (v < m1) { m2 = m1; m1 = v; i1 = p + 2 * kk; } else if (v < m2) m2 = v;
            }
            st[6144 + t] = m1; st[6144 + 2048 + t] = m2; st[6144 + 4096 + t] = (float)i1;
        }
        {   // H axis
            const float* bp = s + l + p * 1024;
            float m1 = 1e30f, m2 = 1e30f; int i1 = -1;
            #pragma unroll
            for (int kk = 0; kk < 16; ++kk) {
                float v = bp[kk * 2048];
                if (v < m1) { m2 = m1; m1 = v; i1 = p + 2 * kk; } else if (v < m2) m2 = v;
            }
            st[12288 + t] = m1; st[12288 + 2048 + t] = m2; st[12288 + 4096 + t] = (float)i1;
        }
    }
    __syncthreads();

    for (int i = tid; i < SSP; i += 1024) {
        const int d = i & 31, w = (i >> 5) & 31, h = i >> 10;
        const float v = s[i];
        const int tD = (((h << 5) | w) << 1) | (d & 1);
        const float eD = ((float)d == st[4096 + tD]) ? st[2048 + tD] : st[tD];
        const int tW = (((h << 5) | d) << 1) | (w & 1);
        const float eW = ((float)w == st[6144 + 4096 + tW]) ? st[6144 + 2048 + tW] : st[6144 + tW];
        const int tH = (((w << 5) | d) << 1) | (h & 1);
        const float eH = ((float)h == st[12288 + 4096 + tH]) ? st[12288 + 2048 + tH] : st[12288 + tH];
        const float val = fmaxf(0.0f, v - fminf(eD, fminf(eW, eH)));
        const __nv_bfloat16 hh = __float2bfloat16(val);
        g_acth[joff + i] = hh;
        g_actl[joff + i] = __float2bfloat16(val - __bfloat162float(hh));
    }
}

// ---------------------------------------------------------------------------
// Kernel 2: W -> bf16 hi/lo, row-major [o][k]
// ---------------------------------------------------------------------------
__global__ void wb_kernel(const float* __restrict__ w) {
    const int i = blockIdx.x * 256 + threadIdx.x;   // 32768 = 128*256
    const float v = w[i];
    const __nv_bfloat16 h = __float2bfloat16(v);
    g_wbh[i] = h;
    g_wbl[i] = __float2bfloat16(v - __bfloat162float(h));
}

// ---------------------------------------------------------------------------
// Marker no-op: keeps gemm at launch slot #4 (the slot ncu captures).
// ---------------------------------------------------------------------------
__global__ void mid_marker_kernel() {}

// ---------------------------------------------------------------------------
// Kernel 3: bf16 split-precision GEMM via HMMA + cp.async 3-stage pipeline.
// D[o(128), s(128)] = sum_k W[o,k]*act[k,s], K=256 in 8 chunks of 32.
// All operands pre-converted bf16 hi/lo. 3 products: AhBh + AhBl + AlBh.
// Triple-buffered SMEM, one __syncthreads per chunk. Fused bias + BN partials.
// Warp grid 2(m) x 4(n): each warp 64(o) x 32(s).
// ---------------------------------------------------------------------------
#define KCH 32
#define NCHUNK 8
#define WP 80                        // W row pitch bytes (40 bf16, 20 words)
#define AP 272                       // act row pitch bytes (136 bf16, 68 words)
#define WH_OFF 0
#define WL_OFF 10240                 // 128*WP
#define AH_OFF 20480
#define AL_OFF 29184                 // 20480 + 32*AP
#define BUF_BYTES 37888              // 29184 + 32*AP
#define GEMM_SMEM (3 * BUF_BYTES)    // 113664

__global__ __launch_bounds__(256, 1) void gemm_kernel(const float* __restrict__ bias,
                                                      float* __restrict__ y) {
    __shared__ float sbias[128];
    const int tid = threadIdx.x, l = tid & 31, wid = tid >> 5;
    const int cta = blockIdx.x, b = cta >> 8, tile = cta & 255;
    const int wm = (wid & 1) * 64;        // o-offset of this warp
    const int wn = (wid >> 1) * 32;       // s-offset of this warp
    const uint32_t smb = smem_u32(dyn_smem);

    if (tid < 128) sbias[tid] = bias[tid];

    // Issue all cp.asyncs for chunk ch into buffer bn (2048 x 16B, 8/thread).
    auto ISSUE = [&](int ch, int bn) {
        const uint32_t bb = smb + bn * BUF_BYTES;
        #pragma unroll
        for (int j = 0; j < 4; ++j) {                    // W hi/lo: 1024 ops
            const int idx = tid + j * 256;
            const int half = idx >> 9;
            const int r = idx & 511, o = r >> 2, g = r & 3;
            const __nv_bfloat16* src = (half ? g_wbl : g_wbh) + o * 256 + ch * KCH + g * 8;
            cpasync16(bb + (half ? WL_OFF : WH_OFF) + o * WP + g * 16, src);
        }
        const size_t abase = ((size_t)b * 256 + ch * KCH) * SSP + (size_t)tile * 128;
        #pragma unroll
        for (int j = 0; j < 4; ++j) {                    // act hi/lo: 1024 ops
            const int idx = tid + j * 256;
            const int half = idx >> 9;
            const int r = idx & 511, row = r >> 4, g = r & 15;
            const __nv_bfloat16* src = (half ? g_actl : g_acth) + abase + (size_t)row * SSP + g * 8;
            cpasync16(bb + (half ? AL_OFF : AH_OFF) + row * AP + g * 16, src);
        }
    };

    ISSUE(0, 0); CP_COMMIT();
    ISSUE(1, 1); CP_COMMIT();

    float acc[16][4];
    #pragma unroll
    for (int i = 0; i < 16; ++i)
        #pragma unroll
        for (int j = 0; j < 4; ++j) acc[i][j] = 0.0f;

    #pragma unroll 1
    for (int ch = 0; ch < NCHUNK; ++ch) {
        if (ch < NCHUNK - 1) asm volatile("cp.async.wait_group 1;" ::: "memory");
        else                 asm volatile("cp.async.wait_group 0;" ::: "memory");
        __syncthreads();
        if (ch + 2 < NCHUNK) { ISSUE(ch + 2, (ch + 2) % 3); CP_COMMIT(); }

        const uint32_t bb = smb + (ch % 3) * BUF_BYTES;
        #pragma unroll
        for (int ks = 0; ks < 2; ++ks) {     // two 16-k steps per 32-chunk
            uint32_t ah[4][4], al[4][4];
            #pragma unroll
            for (int mi = 0; mi < 4; ++mi) {
                const uint32_t ra = bb + (wm + mi * 16 + (l & 15)) * WP
                                    + ks * 32 + (l >> 4) * 16;
                ldsm4(ra + WH_OFF, ah[mi]);
                ldsm4(ra + WL_OFF, al[mi]);
            }
            uint32_t bh[2][4], bl[2][4];
            #pragma unroll
            for (int ng = 0; ng < 2; ++ng) {
                const uint32_t rb = bb + (ks * 16 + (l & 15)) * AP
                                    + (wn + ng * 16 + (l >> 4) * 8) * 2;
                ldsm4t(rb + AH_OFF, bh[ng]);
                ldsm4t(rb + AL_OFF, bl[ng]);
            }
            #pragma unroll
            for (int mi = 0; mi < 4; ++mi)
                #pragma unroll
                for (int ni = 0; ni < 4; ++ni) {
                    float* d = acc[mi * 4 + ni];
                    const uint32_t* hb = &bh[ni >> 1][(ni & 1) * 2];
                    const uint32_t* lb = &bl[ni >> 1][(ni & 1) * 2];
                    mma_bf16(d, ah[mi], hb[0], hb[1]);   // hi*hi
                    mma_bf16(d, ah[mi], lb[0], lb[1]);   // hi*lo
                    mma_bf16(d, al[mi], hb[0], hb[1]);   // lo*hi
                }
        }
        __syncthreads();   // all warps done with buf (ch%3) before it is refilled
    }

    // Epilogue: bias, store y, fused deterministic BN partials.
    const int row = l >> 2, colp = (l & 3) * 2;
    #pragma unroll
    for (int mi = 0; mi < 4; ++mi) {
        #pragma unroll
        for (int rr = 0; rr < 2; ++rr) {
            const int o = wm + mi * 16 + row + rr * 8;
            const float bo = sbias[o];
            float s1 = 0.0f, s2 = 0.0f;
            float* obase = y + ((size_t)(b * 128 + o)) * SSP + tile * 128 + wn + colp;
            #pragma unroll
            for (int ni = 0; ni < 4; ++ni) {
                const float v0 = acc[mi * 4 + ni][rr * 2 + 0] + bo;
                const float v1 = acc[mi * 4 + ni][rr * 2 + 1] + bo;
                *(float2*)(obase + ni * 8) = make_float2(v0, v1);
                s1 += v0 + v1;
                s2 += v0 * v0 + v1 * v1;
            }
            s1 += __shfl_xor_sync(0xffffffffu, s1, 1);
            s2 += __shfl_xor_sync(0xffffffffu, s2, 1);
            s1 += __shfl_xor_sync(0xffffffffu, s1, 2);
            s2 += __shfl_xor_sync(0xffffffffu, s2, 2);
            if ((l & 3) == 0) {
                const int pidx = (cta * 4 + (wid >> 1)) * 128 + o;
                g_part[pidx] = s1;
                g_part[NPART * 128 + pidx] = s2;
            }
        }
    }
}

// ---------------------------------------------------------------------------
// Kernel 4a/4b: parallel deterministic reduction of partials -> scale/shift
// ---------------------------------------------------------------------------
__global__ void stats1_kernel() {
    __shared__ float r1[256], r2[256];
    const int bb = blockIdx.x;           // 0..63
    const int tid = threadIdx.x;         // 256
    const int o = tid & 127, half = tid >> 7;
    float s1 = 0.0f, s2 = 0.0f;
    for (int c = half; c < 64; c += 2) {
        const int idx = (bb * 64 + c) * 128 + o;
        s1 += g_part[idx];
        s2 += g_part[NPART * 128 + idx];
    }
    r1[tid] = s1; r2[tid] = s2;
    __syncthreads();
    if (half == 0) {
        g_part2[bb * 128 + o] = r1[tid] + r1[tid + 128];
        g_part2[64 * 128 + bb * 128 + o] = r2[tid] + r2[tid + 128];
    }
}

__global__ void stats2_kernel(const float* __restrict__ gamma,
                              const float* __restrict__ beta) {
    const int o = threadIdx.x;
    float s1 = 0.0f, s2 = 0.0f;
    for (int c = 0; c < 64; ++c) {
        s1 += g_part2[c * 128 + o];
        s2 += g_part2[64 * 128 + c * 128 + o];
    }
    const float invN = 1.0f / 131072.0f;
    const float mean = s1 * invN;
    const float var = fmaxf(s2 * invN - mean * mean, 0.0f);
    const float rstd = rsqrtf(var + 1e-5f);
    const float g = gamma[o];
    g_scale[o] = rstd * g;
    g_shift[o] = beta[o] - mean * rstd * g;
}

// ---------------------------------------------------------------------------
// Kernel 5: in-place BN affine + exact-erf GELU
// ---------------------------------------------------------------------------
__global__ __launch_bounds__(256) void bn_gelu_kernel(float* __restrict__ y) {
    const int i4 = blockIdx.x * 256 + threadIdx.x;
    const int o = (i4 >> 13) & 127;
    const float sc = g_scale[o], sh = g_shift[o];
    float4 v = ((float4*)y)[i4];
    float t;
    t = fmaf(v.x, sc, sh); v.x = t * normcdff(t);
    t = fmaf(v.y, sc, sh); v.y = t * normcdff(t);
    t = fmaf(v.z, sc, sh); v.z = t * normcdff(t);
    t = fmaf(v.w, sc, sh); v.w = t * normcdff(t);
    ((float4*)y)[i4] = v;
}

// ---------------------------------------------------------------------------
extern "C" void kernel_launch(void* const* d_in, const int* in_sizes, int n_in,
                              void* d_out, int out_size) {
    const float* x      = (const float*)d_in[0];
    const float* conv_w = (const float*)d_in[1];
    const float* conv_b = (const float*)d_in[2];
    const float* gamma  = (const float*)d_in[3];
    const float* beta   = (const float*)d_in[4];
    float* y = (float*)d_out;

    cudaFuncSetAttribute(xj_kernel, cudaFuncAttributeMaxDynamicSharedMemorySize, 204800);
    cudaFuncSetAttribute(gemm_kernel, cudaFuncAttributeMaxDynamicSharedMemorySize, GEMM_SMEM);

    wb_kernel<<<128, 256>>>(conv_w);            // 1
    xj_kernel<<<512, 1024, 204800>>>(x);        // 2
    mid_marker_kernel<<<1, 32>>>();             // 3 (keeps gemm in ncu's slot)
    gemm_kernel<<<1024, 256, GEMM_SMEM>>>(conv_b, y);   // 4 <- profiled
    stats1_kernel<<<64, 256>>>();               // 5
    stats2_kernel<<<1, 128>>>(gamma, beta);     // 6
    bn_gelu_kernel<<<16384, 256>>>(y);          // 7
}

// round 9
// speedup vs baseline: 1.2222x; 1.2222x over previous
#include <cuda_runtime.h>
#include <cuda_bf16.h>
#include <cstdint>

// Problem constants
#define SSP 32768           // H*W*D
#define NB 4
#define NPART 4096          // gemm partials: 1024 CTAs * 4 n-warp-groups

// Scratch (no allocations allowed)
__device__ __align__(16) __nv_bfloat16 g_acth[NB * 256 * SSP];  // act hi: [b][k=256][s], 64MB
__device__ __align__(16) __nv_bfloat16 g_actl[NB * 256 * SSP];  // act lo, 64MB
__device__ __align__(16) __nv_bfloat16 g_wbh[128 * 256];        // W hi, row-major [o][k]
__device__ __align__(16) __nv_bfloat16 g_wbl[128 * 256];        // W lo, row-major [o][k]
__device__ float g_part[2 * NPART * 128];
__device__ float g_part2[2 * 64 * 128];
__device__ float g_scale[128];
__device__ float g_shift[128];

// Single dynamic-SMEM symbol shared by all kernels.
extern __shared__ char dyn_smem[];

// ---------------------------------------------------------------------------
// PTX helpers (sm_80+; valid under plain sm_100 target)
// ---------------------------------------------------------------------------
__device__ __forceinline__ uint32_t smem_u32(const void* p) {
    uint32_t a;
    asm("{ .reg .u64 t; cvta.to.shared.u64 t, %1; cvt.u32.u64 %0, t; }" : "=r"(a) : "l"(p));
    return a;
}
__device__ __forceinline__ void cpasync16(uint32_t sa, const void* ga) {
    asm volatile("cp.async.cg.shared.global [%0], [%1], 16;" :: "r"(sa), "l"(ga) : "memory");
}
#define CP_COMMIT() asm volatile("cp.async.commit_group;" ::: "memory")
__device__ __forceinline__ void ldsm4(uint32_t addr, uint32_t* r) {
    asm volatile("ldmatrix.sync.aligned.m8n8.x4.shared.b16 {%0,%1,%2,%3}, [%4];"
                 : "=r"(r[0]), "=r"(r[1]), "=r"(r[2]), "=r"(r[3]) : "r"(addr));
}
__device__ __forceinline__ void ldsm4t(uint32_t addr, uint32_t* r) {
    asm volatile("ldmatrix.sync.aligned.m8n8.x4.trans.shared.b16 {%0,%1,%2,%3}, [%4];"
                 : "=r"(r[0]), "=r"(r[1]), "=r"(r[2]), "=r"(r[3]) : "r"(addr));
}
__device__ __forceinline__ void mma_bf16(float* d, const uint32_t* a, uint32_t b0, uint32_t b1) {
    asm volatile("mma.sync.aligned.m16n8k16.row.col.f32.bf16.bf16.f32 "
                 "{%0,%1,%2,%3}, {%4,%5,%6,%7}, {%8,%9}, {%0,%1,%2,%3};"
                 : "+f"(d[0]), "+f"(d[1]), "+f"(d[2]), "+f"(d[3])
                 : "r"(a[0]), "r"(a[1]), "r"(a[2]), "r"(a[3]), "r"(b0), "r"(b1));
}

// ---------------------------------------------------------------------------
// Kernel 1: x_j + fp32->bf16 hi/lo conversion of BOTH act halves.
// SMEM slice padded to 33-float row pitch: sidx(h,w,d)=(h*32+w)*33+d, so the
// per-axis stats loops hit distinct banks (<=2-way) instead of 16-way on D.
// ---------------------------------------------------------------------------
#define SPITCH 33
#define SLICE_F (1024 * SPITCH)               // 33792 floats
#define XJ_SMEM ((SLICE_F + 18432) * 4)       // 208896 bytes

__global__ __launch_bounds__(1024) void xj_kernel(const float* __restrict__ x) {
    float* s  = (float*)dyn_smem;             // padded [h*32+w][33]
    float* st = (float*)dyn_smem + SLICE_F;   // stats: [axis][3][2048]
    const int tid = threadIdx.x;
    const int bidx = blockIdx.x;                 // b*128 + c
    const int b = bidx >> 7, c = bidx & 127;
    const size_t base = (size_t)bidx * SSP;
    const size_t xoff = ((size_t)b * 256 + c) * SSP;          // act k = c
    const size_t joff = ((size_t)b * 256 + 128 + c) * SSP;    // act k = 128+c

    for (int i = tid; i < SSP; i += 1024) {
        const float v = x[base + i];
        s[(i >> 5) * SPITCH + (i & 31)] = v;
        const __nv_bfloat16 h = __float2bfloat16(v);
        g_acth[xoff + i] = h;
        g_actl[xoff + i] = __float2bfloat16(v - __bfloat162float(h));
    }
    __syncthreads();

    for (int t = tid; t < 2048; t += 1024) {
        const int l = t >> 1, p = t & 1;
        {   // D axis: line (h,w)=l -> base l*33 + p, step 2
            const float* bp = s + l * SPITCH + p;
            float m1 = 1e30f, m2 = 1e30f; int i1 = -1;
            #pragma unroll
            for (int kk = 0; kk < 16; ++kk) {
                float v = bp[kk * 2];
                if (v < m1) { m2 = m1; m1 = v; i1 = p + 2 * kk; } else if (v < m2) m2 = v;
            }
            st[t] = m1; st[2048 + t] = m2; st[4096 + t] = (float)i1;
        }
        {   // W axis: line (h,d): h=l>>5, d=l&31 -> base h*1056 + d + p*33, step 66
            const float* bp = s + (l >> 5) * (32 * SPITCH) + (l & 31) + p * SPITCH;
            float m1 = 1e30f, m2 = 1e30f; int i1 = -1;
            #pragma unroll
            for (int kk = 0; kk < 16; ++kk) {
                float v = bp[kk * (2 * SPITCH)];
                if (v < m1) { m2 = m1; m1 = v; i1 = p + 2 * kk; } else if (v < m2) m2 = v;
            }
            st[6144 + t] = m1; st[6144 + 2048 + t] = m2; st[6144 + 4096 + t] = (float)i1;
        }
        {   // H axis: line (w,d): w=l>>5, d=l&31 -> base w*33 + d + p*1056, step 2112
            const float* bp = s + (l >> 5) * SPITCH + (l & 31) + p * (32 * SPITCH);
            float m1 = 1e30f, m2 = 1e30f; int i1 = -1;
            #pragma unroll
            for (int kk = 0; kk < 16; ++kk) {
                float v = bp[kk * (64 * SPITCH)];
                if (v < m1) { m2 = m1; m1 = v; i1 = p + 2 * kk; } else if (v < m2) m2 = v;
            }
            st[12288 + t] = m1; st[12288 + 2048 + t] = m2; st[12288 + 4096 + t] = (float)i1;
        }
    }
    __syncthreads();

    for (int i = tid; i < SSP; i += 1024) {
        const int d = i & 31, w = (i >> 5) & 31, h = i >> 10;
        const float v = s[(i >> 5) * SPITCH + d];
        const int tD = (((h << 5) | w) << 1) | (d & 1);
        const float eD = ((float)d == st[4096 + tD]) ? st[2048 + tD] : st[tD];
        const int tW = (((h << 5) | d) << 1) | (w & 1);
        const float eW = ((float)w == st[6144 + 4096 + tW]) ? st[6144 + 2048 + tW] : st[6144 + tW];
        const int tH = (((w << 5) | d) << 1) | (h & 1);
        const float eH = ((float)h == st[12288 + 4096 + tH]) ? st[12288 + 2048 + tH] : st[12288 + tH];
        const float val = fmaxf(0.0f, v - fminf(eD, fminf(eW, eH)));
        const __nv_bfloat16 hh = __float2bfloat16(val);
        g_acth[joff + i] = hh;
        g_actl[joff + i] = __float2bfloat16(val - __bfloat162float(hh));
    }
}

// ---------------------------------------------------------------------------
// Kernel 2: W -> bf16 hi/lo, row-major [o][k]
// ---------------------------------------------------------------------------
__global__ void wb_kernel(const float* __restrict__ w) {
    const int i = blockIdx.x * 256 + threadIdx.x;   // 32768 = 128*256
    const float v = w[i];
    const __nv_bfloat16 h = __float2bfloat16(v);
    g_wbh[i] = h;
    g_wbl[i] = __float2bfloat16(v - __bfloat162float(h));
}

// ---------------------------------------------------------------------------
// Marker no-op: keeps gemm at the ncu-captured launch slot.
// ---------------------------------------------------------------------------
__global__ void mid_marker_kernel() {}

// ---------------------------------------------------------------------------
// Kernel 3: bf16 split-precision GEMM via HMMA + cp.async 2-stage pipeline,
// 2 CTAs/SM (the round-8 profile showed occ=12.4%, tensor=45% -> sync bubbles
// with nothing to backfill). 75776B SMEM/CTA, regs capped via launch_bounds.
// ---------------------------------------------------------------------------
#define KCH 32
#define NCHUNK 8
#define WP 80                        // W row pitch bytes (40 bf16)
#define AP 272                       // act row pitch bytes (136 bf16)
#define WH_OFF 0
#define WL_OFF 10240                 // 128*WP
#define AH_OFF 20480
#define AL_OFF 29184                 // 20480 + 32*AP
#define BUF_BYTES 37888              // 29184 + 32*AP
#define GEMM_SMEM (2 * BUF_BYTES)    // 75776

__global__ __launch_bounds__(256, 2) void gemm_kernel(const float* __restrict__ bias,
                                                      float* __restrict__ y) {
    __shared__ float sbias[128];
    const int tid = threadIdx.x, l = tid & 31, wid = tid >> 5;
    const int cta = blockIdx.x, b = cta >> 8, tile = cta & 255;
    const int wm = (wid & 1) * 64;        // o-offset of this warp
    const int wn = (wid >> 1) * 32;       // s-offset of this warp
    const uint32_t smb = smem_u32(dyn_smem);

    if (tid < 128) sbias[tid] = bias[tid];

    // Issue all cp.asyncs for chunk ch into buffer bn (2048 x 16B, 8/thread).
    auto ISSUE = [&](int ch, int bn) {
        const uint32_t bb = smb + bn * BUF_BYTES;
        #pragma unroll
        for (int j = 0; j < 4; ++j) {                    // W hi/lo: 1024 ops
            const int idx = tid + j * 256;
            const int half = idx >> 9;
            const int r = idx & 511, o = r >> 2, g = r & 3;
            const __nv_bfloat16* src = (half ? g_wbl : g_wbh) + o * 256 + ch * KCH + g * 8;
            cpasync16(bb + (half ? WL_OFF : WH_OFF) + o * WP + g * 16, src);
        }
        const size_t abase = ((size_t)b * 256 + ch * KCH) * SSP + (size_t)tile * 128;
        #pragma unroll
        for (int j = 0; j < 4; ++j) {                    // act hi/lo: 1024 ops
            const int idx = tid + j * 256;
            const int half = idx >> 9;
            const int r = idx & 511, row = r >> 4, g = r & 15;
            const __nv_bfloat16* src = (half ? g_actl : g_acth) + abase + (size_t)row * SSP + g * 8;
            cpasync16(bb + (half ? AL_OFF : AH_OFF) + row * AP + g * 16, src);
        }
    };

    ISSUE(0, 0); CP_COMMIT();
    ISSUE(1, 1); CP_COMMIT();

    float acc[16][4];
    #pragma unroll
    for (int i = 0; i < 16; ++i)
        #pragma unroll
        for (int j = 0; j < 4; ++j) acc[i][j] = 0.0f;

    #pragma unroll 1
    for (int ch = 0; ch < NCHUNK; ++ch) {
        if (ch < NCHUNK - 1) asm volatile("cp.async.wait_group 1;" ::: "memory");
        else                 asm volatile("cp.async.wait_group 0;" ::: "memory");
        __syncthreads();

        const uint32_t bb = smb + (ch & 1) * BUF_BYTES;
        #pragma unroll
        for (int ks = 0; ks < 2; ++ks) {     // two 16-k steps per 32-chunk
            uint32_t bh[2][4], bl[2][4];
            #pragma unroll
            for (int ng = 0; ng < 2; ++ng) {
                const uint32_t rb = bb + (ks * 16 + (l & 15)) * AP
                                    + (wn + ng * 16 + (l >> 4) * 8) * 2;
                ldsm4t(rb + AH_OFF, bh[ng]);
                ldsm4t(rb + AL_OFF, bl[ng]);
            }
            #pragma unroll
            for (int mi = 0; mi < 4; ++mi) {
                uint32_t ah[4], al[4];
                const uint32_t ra = bb + (wm + mi * 16 + (l & 15)) * WP
                                    + ks * 32 + (l >> 4) * 16;
                ldsm4(ra + WH_OFF, ah);
                ldsm4(ra + WL_OFF, al);
                #pragma unroll
                for (int ni = 0; ni < 4; ++ni) {
                    float* d = acc[mi * 4 + ni];
                    const uint32_t* hb = &bh[ni >> 1][(ni & 1) * 2];
                    const uint32_t* lb = &bl[ni >> 1][(ni & 1) * 2];
                    mma_bf16(d, ah, hb[0], hb[1]);   // hi*hi
                    mma_bf16(d, ah, lb[0], lb[1]);   // hi*lo
                    mma_bf16(d, al, hb[0], hb[1]);   // lo*hi
                }
            }
        }
        __syncthreads();   // all warps done with buf (ch&1) before refill
        if (ch + 2 < NCHUNK) { ISSUE(ch + 2, ch & 1); CP_COMMIT(); }
    }

    // Epilogue: bias, store y, fused deterministic BN partials.
    const int row = l >> 2, colp = (l & 3) * 2;
    #pragma unroll
    for (int mi = 0; mi < 4; ++mi) {
        #pragma unroll
        for (int rr = 0; rr < 2; ++rr) {
            const int o = wm + mi * 16 + row + rr * 8;
            const float bo = sbias[o];
            float s1 = 0.0f, s2 = 0.0f;
            float* obase = y + ((size_t)(b * 128 + o)) * SSP + tile * 128 + wn + colp;
            #pragma unroll
            for (int ni = 0; ni < 4; ++ni) {
                const float v0 = acc[mi * 4 + ni][rr * 2 + 0] + bo;
                const float v1 = acc[mi * 4 + ni][rr * 2 + 1] + bo;
                *(float2*)(obase + ni * 8) = make_float2(v0, v1);
                s1 += v0 + v1;
                s2 += v0 * v0 + v1 * v1;
            }
            s1 += __shfl_xor_sync(0xffffffffu, s1, 1);
            s2 += __shfl_xor_sync(0xffffffffu, s2, 1);
            s1 += __shfl_xor_sync(0xffffffffu, s1, 2);
            s2 += __shfl_xor_sync(0xffffffffu, s2, 2);
            if ((l & 3) == 0) {
                const int pidx = (cta * 4 + (wid >> 1)) * 128 + o;
                g_part[pidx] = s1;
                g_part[NPART * 128 + pidx] = s2;
            }
        }
    }
}

// ---------------------------------------------------------------------------
// Kernel 4a/4b: parallel deterministic reduction of partials -> scale/shift
// ---------------------------------------------------------------------------
__global__ void stats1_kernel() {
    __shared__ float r1[256], r2[256];
    const int bb = blockIdx.x;           // 0..63
    const int tid = threadIdx.x;         // 256
    const int o = tid & 127, half = tid >> 7;
    float s1 = 0.0f, s2 = 0.0f;
    for (int c = half; c < 64; c += 2) {
        const int idx = (bb * 64 + c) * 128 + o;
        s1 += g_part[idx];
        s2 += g_part[NPART * 128 + idx];
    }
    r1[tid] = s1; r2[tid] = s2;
    __syncthreads();
    if (half == 0) {
        g_part2[bb * 128 + o] = r1[tid] + r1[tid + 128];
        g_part2[64 * 128 + bb * 128 + o] = r2[tid] + r2[tid + 128];
    }
}

__global__ void stats2_kernel(const float* __restrict__ gamma,
                              const float* __restrict__ beta) {
    const int o = threadIdx.x;
    float s1 = 0.0f, s2 = 0.0f;
    for (int c = 0; c < 64; ++c) {
        s1 += g_part2[c * 128 + o];
        s2 += g_part2[64 * 128 + c * 128 + o];
    }
    const float invN = 1.0f / 131072.0f;
    const float mean = s1 * invN;
    const float var = fmaxf(s2 * invN - mean * mean, 0.0f);
    const float rstd = rsqrtf(var + 1e-5f);
    const float g = gamma[o];
    g_scale[o] = rstd * g;
    g_shift[o] = beta[o] - mean * rstd * g;
}

// ---------------------------------------------------------------------------
// Kernel 5: in-place BN affine + exact-erf GELU
// ---------------------------------------------------------------------------
__global__ __launch_bounds__(256) void bn_gelu_kernel(float* __restrict__ y) {
    const int i4 = blockIdx.x * 256 + threadIdx.x;
    const int o = (i4 >> 13) & 127;
    const float sc = g_scale[o], sh = g_shift[o];
    float4 v = ((float4*)y)[i4];
    float t;
    t = fmaf(v.x, sc, sh); v.x = t * normcdff(t);
    t = fmaf(v.y, sc, sh); v.y = t * normcdff(t);
    t = fmaf(v.z, sc, sh); v.z = t * normcdff(t);
    t = fmaf(v.w, sc, sh); v.w = t * normcdff(t);
    ((float4*)y)[i4] = v;
}

// ---------------------------------------------------------------------------
extern "C" void kernel_launch(void* const* d_in, const int* in_sizes, int n_in,
                              void* d_out, int out_size) {
    const float* x      = (const float*)d_in[0];
    const float* conv_w = (const float*)d_in[1];
    const float* conv_b = (const float*)d_in[2];
    const float* gamma  = (const float*)d_in[3];
    const float* beta   = (const float*)d_in[4];
    float* y = (float*)d_out;

    cudaFuncSetAttribute(xj_kernel, cudaFuncAttributeMaxDynamicSharedMemorySize, XJ_SMEM);
    cudaFuncSetAttribute(gemm_kernel, cudaFuncAttributeMaxDynamicSharedMemorySize, GEMM_SMEM);

    wb_kernel<<<128, 256>>>(conv_w);            // 1
    xj_kernel<<<512, 1024, XJ_SMEM>>>(x);       // 2
    mid_marker_kernel<<<1, 32>>>();             // 3 (keeps gemm in ncu's slot)
    gemm_kernel<<<1024, 256, GEMM_SMEM>>>(conv_b, y);   // 4 <- profiled
    stats1_kernel<<<64, 256>>>();               // 5
    stats2_kernel<<<1, 128>>>(gamma, beta);     // 6
    bn_gelu_kernel<<<16384, 256>>>(y);          // 7
}

// round 10
// speedup vs baseline: 1.2317x; 1.0077x over previous
#include <cuda_runtime.h>
#include <cuda_bf16.h>
#include <cstdint>

// Problem constants
#define SSP 32768           // H*W*D
#define NB 4
#define NPART 4096          // gemm partials: 1024 CTAs * 4 n-warp-groups

// Scratch (no allocations allowed)
__device__ __align__(16) __nv_bfloat16 g_acth[NB * 256 * SSP];  // act hi: [b][k=256][s], 64MB
__device__ __align__(16) __nv_bfloat16 g_actl[NB * 256 * SSP];  // act lo, 64MB
__device__ __align__(16) __nv_bfloat16 g_wbh[128 * 256];        // W hi, row-major [o][k]
__device__ __align__(16) __nv_bfloat16 g_wbl[128 * 256];        // W lo, row-major [o][k]
__device__ float g_part[2 * NPART * 128];
__device__ float g_part2[2 * 64 * 128];
__device__ float g_scale[128];
__device__ float g_shift[128];

// Single dynamic-SMEM symbol shared by all kernels.
extern __shared__ char dyn_smem[];

// ---------------------------------------------------------------------------
// PTX helpers (sm_80+; valid under plain sm_100 target)
// ---------------------------------------------------------------------------
__device__ __forceinline__ uint32_t smem_u32(const void* p) {
    uint32_t a;
    asm("{ .reg .u64 t; cvta.to.shared.u64 t, %1; cvt.u32.u64 %0, t; }" : "=r"(a) : "l"(p));
    return a;
}
__device__ __forceinline__ void cpasync16(uint32_t sa, const void* ga) {
    asm volatile("cp.async.cg.shared.global [%0], [%1], 16;" :: "r"(sa), "l"(ga) : "memory");
}
#define CP_COMMIT() asm volatile("cp.async.commit_group;" ::: "memory")
__device__ __forceinline__ void ldsm4(uint32_t addr, uint32_t* r) {
    asm volatile("ldmatrix.sync.aligned.m8n8.x4.shared.b16 {%0,%1,%2,%3}, [%4];"
                 : "=r"(r[0]), "=r"(r[1]), "=r"(r[2]), "=r"(r[3]) : "r"(addr));
}
__device__ __forceinline__ void ldsm4t(uint32_t addr, uint32_t* r) {
    asm volatile("ldmatrix.sync.aligned.m8n8.x4.trans.shared.b16 {%0,%1,%2,%3}, [%4];"
                 : "=r"(r[0]), "=r"(r[1]), "=r"(r[2]), "=r"(r[3]) : "r"(addr));
}
__device__ __forceinline__ void mma_bf16(float* d, const uint32_t* a, uint32_t b0, uint32_t b1) {
    asm volatile("mma.sync.aligned.m16n8k16.row.col.f32.bf16.bf16.f32 "
                 "{%0,%1,%2,%3}, {%4,%5,%6,%7}, {%8,%9}, {%0,%1,%2,%3};"
                 : "+f"(d[0]), "+f"(d[1]), "+f"(d[2]), "+f"(d[3])
                 : "r"(a[0]), "r"(a[1]), "r"(a[2]), "r"(a[3]), "r"(b0), "r"(b1));
}

// ---------------------------------------------------------------------------
// Kernel 1: x_j + fp32->bf16 hi/lo conversion of BOTH act halves.
// SMEM slice padded to 33-float row pitch (bank-conflict-free axis scans).
// ---------------------------------------------------------------------------
#define SPITCH 33
#define SLICE_F (1024 * SPITCH)               // 33792 floats
#define XJ_SMEM ((SLICE_F + 18432) * 4)       // 208896 bytes

__global__ __launch_bounds__(1024) void xj_kernel(const float* __restrict__ x) {
    float* s  = (float*)dyn_smem;             // padded [h*32+w][33]
    float* st = (float*)dyn_smem + SLICE_F;   // stats: [axis][3][2048]
    const int tid = threadIdx.x;
    const int bidx = blockIdx.x;                 // b*128 + c
    const int b = bidx >> 7, c = bidx & 127;
    const size_t base = (size_t)bidx * SSP;
    const size_t xoff = ((size_t)b * 256 + c) * SSP;          // act k = c
    const size_t joff = ((size_t)b * 256 + 128 + c) * SSP;    // act k = 128+c

    for (int i = tid; i < SSP; i += 1024) {
        const float v = x[base + i];
        s[(i >> 5) * SPITCH + (i & 31)] = v;
        const __nv_bfloat16 h = __float2bfloat16(v);
        g_acth[xoff + i] = h;
        g_actl[xoff + i] = __float2bfloat16(v - __bfloat162float(h));
    }
    __syncthreads();

    for (int t = tid; t < 2048; t += 1024) {
        const int l = t >> 1, p = t & 1;
        {   // D axis
            const float* bp = s + l * SPITCH + p;
            float m1 = 1e30f, m2 = 1e30f; int i1 = -1;
            #pragma unroll
            for (int kk = 0; kk < 16; ++kk) {
                float v = bp[kk * 2];
                if (v < m1) { m2 = m1; m1 = v; i1 = p + 2 * kk; } else if (v < m2) m2 = v;
            }
            st[t] = m1; st[2048 + t] = m2; st[4096 + t] = (float)i1;
        }
        {   // W axis
            const float* bp = s + (l >> 5) * (32 * SPITCH) + (l & 31) + p * SPITCH;
            float m1 = 1e30f, m2 = 1e30f; int i1 = -1;
            #pragma unroll
            for (int kk = 0; kk < 16; ++kk) {
                float v = bp[kk * (2 * SPITCH)];
                if (v < m1) { m2 = m1; m1 = v; i1 = p + 2 * kk; } else if (v < m2) m2 = v;
            }
            st[6144 + t] = m1; st[6144 + 2048 + t] = m2; st[6144 + 4096 + t] = (float)i1;
        }
        {   // H axis
            const float* bp = s + (l >> 5) * SPITCH + (l & 31) + p * (32 * SPITCH);
            float m1 = 1e30f, m2 = 1e30f; int i1 = -1;
            #pragma unroll
            for (int kk = 0; kk < 16; ++kk) {
                float v = bp[kk * (64 * SPITCH)];
                if (v < m1) { m2 = m1; m1 = v; i1 = p + 2 * kk; } else if (v < m2) m2 = v;
            }
            st[12288 + t] = m1; st[12288 + 2048 + t] = m2; st[12288 + 4096 + t] = (float)i1;
        }
    }
    __syncthreads();

    for (int i = tid; i < SSP; i += 1024) {
        const int d = i & 31, w = (i >> 5) & 31, h = i >> 10;
        const float v = s[(i >> 5) * SPITCH + d];
        const int tD = (((h << 5) | w) << 1) | (d & 1);
        const float eD = ((float)d == st[4096 + tD]) ? st[2048 + tD] : st[tD];
        const int tW = (((h << 5) | d) << 1) | (w & 1);
        const float eW = ((float)w == st[6144 + 4096 + tW]) ? st[6144 + 2048 + tW] : st[6144 + tW];
        const int tH = (((w << 5) | d) << 1) | (h & 1);
        const float eH = ((float)h == st[12288 + 4096 + tH]) ? st[12288 + 2048 + tH] : st[12288 + tH];
        const float val = fmaxf(0.0f, v - fminf(eD, fminf(eW, eH)));
        const __nv_bfloat16 hh = __float2bfloat16(val);
        g_acth[joff + i] = hh;
        g_actl[joff + i] = __float2bfloat16(val - __bfloat162float(hh));
    }
}

// ---------------------------------------------------------------------------
// Kernel 2: W -> bf16 hi/lo, row-major [o][k]
// ---------------------------------------------------------------------------
__global__ void wb_kernel(const float* __restrict__ w) {
    const int i = blockIdx.x * 256 + threadIdx.x;   // 32768 = 128*256
    const float v = w[i];
    const __nv_bfloat16 h = __float2bfloat16(v);
    g_wbh[i] = h;
    g_wbl[i] = __float2bfloat16(v - __bfloat162float(h));
}

// ---------------------------------------------------------------------------
// Marker no-op: keeps gemm at the ncu-captured launch slot.
// ---------------------------------------------------------------------------
__global__ void mid_marker_kernel() {}

// ---------------------------------------------------------------------------
// Kernel 3: bf16 split-precision GEMM via HMMA + cp.async 3-stage pipeline,
// 2 CTAs/SM, ONE __syncthreads per chunk. (R9 profile: tensor=55.9%, DRAM=25%
// -> barrier/wait bound. 3 stages make the top-of-chunk barrier sufficient to
// protect the refill slot: slot (ch+2)%3 was last consumed at chunk ch-1,
// and the barrier proves all warps finished ch-1.)
// ---------------------------------------------------------------------------
#define KCH 32
#define NCHUNK 8
#define WP 80                        // W row pitch bytes (40 bf16)
#define AP 272                       // act row pitch bytes (136 bf16)
#define WH_OFF 0
#define WL_OFF 10240                 // 128*WP
#define AH_OFF 20480
#define AL_OFF 29184                 // 20480 + 32*AP
#define BUF_BYTES 37888              // 29184 + 32*AP
#define GEMM_SMEM (3 * BUF_BYTES)    // 113664

__global__ __launch_bounds__(256, 2) void gemm_kernel(const float* __restrict__ bias,
                                                      float* __restrict__ y) {
    __shared__ float sbias[128];
    const int tid = threadIdx.x, l = tid & 31, wid = tid >> 5;
    const int cta = blockIdx.x, b = cta >> 8, tile = cta & 255;
    const int wm = (wid & 1) * 64;        // o-offset of this warp
    const int wn = (wid >> 1) * 32;       // s-offset of this warp
    const uint32_t smb = smem_u32(dyn_smem);

    if (tid < 128) sbias[tid] = bias[tid];

    // Issue all cp.asyncs for chunk ch into buffer bn (2048 x 16B, 8/thread).
    auto ISSUE = [&](int ch, int bn) {
        const uint32_t bb = smb + bn * BUF_BYTES;
        #pragma unroll
        for (int j = 0; j < 4; ++j) {                    // W hi/lo: 1024 ops
            const int idx = tid + j * 256;
            const int half = idx >> 9;
            const int r = idx & 511, o = r >> 2, g = r & 3;
            const __nv_bfloat16* src = (half ? g_wbl : g_wbh) + o * 256 + ch * KCH + g * 8;
            cpasync16(bb + (half ? WL_OFF : WH_OFF) + o * WP + g * 16, src);
        }
        const size_t abase = ((size_t)b * 256 + ch * KCH) * SSP + (size_t)tile * 128;
        #pragma unroll
        for (int j = 0; j < 4; ++j) {                    // act hi/lo: 1024 ops
            const int idx = tid + j * 256;
            const int half = idx >> 9;
            const int r = idx & 511, row = r >> 4, g = r & 15;
            const __nv_bfloat16* src = (half ? g_actl : g_acth) + abase + (size_t)row * SSP + g * 8;
            cpasync16(bb + (half ? AL_OFF : AH_OFF) + row * AP + g * 16, src);
        }
    };

    ISSUE(0, 0); CP_COMMIT();
    ISSUE(1, 1); CP_COMMIT();

    float acc[16][4];
    #pragma unroll
    for (int i = 0; i < 16; ++i)
        #pragma unroll
        for (int j = 0; j < 4; ++j) acc[i][j] = 0.0f;

    int slot = 0, fill = 2;            // slot = buffer for chunk ch; fill = next free slot
    #pragma unroll 1
    for (int ch = 0; ch < NCHUNK; ++ch) {
        if (ch < NCHUNK - 1) asm volatile("cp.async.wait_group 1;" ::: "memory");
        else                 asm volatile("cp.async.wait_group 0;" ::: "memory");
        __syncthreads();   // chunk ch data visible; all warps done with chunk ch-1
        if (ch + 2 < NCHUNK) { ISSUE(ch + 2, fill); CP_COMMIT(); }

        const uint32_t bb = smb + slot * BUF_BYTES;
        #pragma unroll
        for (int ks = 0; ks < 2; ++ks) {     // two 16-k steps per 32-chunk
            uint32_t bh[2][4], bl[2][4];
            #pragma unroll
            for (int ng = 0; ng < 2; ++ng) {
                const uint32_t rb = bb + (ks * 16 + (l & 15)) * AP
                                    + (wn + ng * 16 + (l >> 4) * 8) * 2;
                ldsm4t(rb + AH_OFF, bh[ng]);
                ldsm4t(rb + AL_OFF, bl[ng]);
            }
            #pragma unroll
            for (int mi = 0; mi < 4; ++mi) {
                uint32_t ah[4], al[4];
                const uint32_t ra = bb + (wm + mi * 16 + (l & 15)) * WP
                                    + ks * 32 + (l >> 4) * 16;
                ldsm4(ra + WH_OFF, ah);
                ldsm4(ra + WL_OFF, al);
                #pragma unroll
                for (int ni = 0; ni < 4; ++ni) {
                    float* d = acc[mi * 4 + ni];
                    const uint32_t* hb = &bh[ni >> 1][(ni & 1) * 2];
                    const uint32_t* lb = &bl[ni >> 1][(ni & 1) * 2];
                    mma_bf16(d, ah, hb[0], hb[1]);   // hi*hi
                    mma_bf16(d, ah, lb[0], lb[1]);   // hi*lo
                    mma_bf16(d, al, hb[0], hb[1]);   // lo*hi
                }
            }
        }
        slot = (slot + 1 == 3) ? 0 : slot + 1;
        fill = (fill + 1 == 3) ? 0 : fill + 1;
    }

    // Epilogue: bias, store y, fused deterministic BN partials.
    const int row = l >> 2, colp = (l & 3) * 2;
    #pragma unroll
    for (int mi = 0; mi < 4; ++mi) {
        #pragma unroll
        for (int rr = 0; rr < 2; ++rr) {
            const int o = wm + mi * 16 + row + rr * 8;
            const float bo = sbias[o];
            float s1 = 0.0f, s2 = 0.0f;
            float* obase = y + ((size_t)(b * 128 + o)) * SSP + tile * 128 + wn + colp;
            #pragma unroll
            for (int ni = 0; ni < 4; ++ni) {
                const float v0 = acc[mi * 4 + ni][rr * 2 + 0] + bo;
                const float v1 = acc[mi * 4 + ni][rr * 2 + 1] + bo;
                *(float2*)(obase + ni * 8) = make_float2(v0, v1);
                s1 += v0 + v1;
                s2 += v0 * v0 + v1 * v1;
            }
            s1 += __shfl_xor_sync(0xffffffffu, s1, 1);
            s2 += __shfl_xor_sync(0xffffffffu, s2, 1);
            s1 += __shfl_xor_sync(0xffffffffu, s1, 2);
            s2 += __shfl_xor_sync(0xffffffffu, s2, 2);
            if ((l & 3) == 0) {
                const int pidx = (cta * 4 + (wid >> 1)) * 128 + o;
                g_part[pidx] = s1;
                g_part[NPART * 128 + pidx] = s2;
            }
        }
    }
}

// ---------------------------------------------------------------------------
// Kernel 4a/4b: parallel deterministic reduction of partials -> scale/shift
// ---------------------------------------------------------------------------
__global__ void stats1_kernel() {
    __shared__ float r1[256], r2[256];
    const int bb = blockIdx.x;           // 0..63
    const int tid = threadIdx.x;         // 256
    const int o = tid & 127, half = tid >> 7;
    float s1 = 0.0f, s2 = 0.0f;
    for (int c = half; c < 64; c += 2) {
        const int idx = (bb * 64 + c) * 128 + o;
        s1 += g_part[idx];
        s2 += g_part[NPART * 128 + idx];
    }
    r1[tid] = s1; r2[tid] = s2;
    __syncthreads();
    if (half == 0) {
        g_part2[bb * 128 + o] = r1[tid] + r1[tid + 128];
        g_part2[64 * 128 + bb * 128 + o] = r2[tid] + r2[tid + 128];
    }
}

__global__ void stats2_kernel(const float* __restrict__ gamma,
                              const float* __restrict__ beta) {
    const int o = threadIdx.x;
    float s1 = 0.0f, s2 = 0.0f;
    for (int c = 0; c < 64; ++c) {
        s1 += g_part2[c * 128 + o];
        s2 += g_part2[64 * 128 + c * 128 + o];
    }
    const float invN = 1.0f / 131072.0f;
    const float mean = s1 * invN;
    const float var = fmaxf(s2 * invN - mean * mean, 0.0f);
    const float rstd = rsqrtf(var + 1e-5f);
    const float g = gamma[o];
    g_scale[o] = rstd * g;
    g_shift[o] = beta[o] - mean * rstd * g;
}

// ---------------------------------------------------------------------------
// Kernel 5: in-place BN affine + exact-erf GELU
// ---------------------------------------------------------------------------
__global__ __launch_bounds__(256) void bn_gelu_kernel(float* __restrict__ y) {
    const int i4 = blockIdx.x * 256 + threadIdx.x;
    const int o = (i4 >> 13) & 127;
    const float sc = g_scale[o], sh = g_shift[o];
    float4 v = ((float4*)y)[i4];
    float t;
    t = fmaf(v.x, sc, sh); v.x = t * normcdff(t);
    t = fmaf(v.y, sc, sh); v.y = t * normcdff(t);
    t = fmaf(v.z, sc, sh); v.z = t * normcdff(t);
    t = fmaf(v.w, sc, sh); v.w = t * normcdff(t);
    ((float4*)y)[i4] = v;
}

// ---------------------------------------------------------------------------
extern "C" void kernel_launch(void* const* d_in, const int* in_sizes, int n_in,
                              void* d_out, int out_size) {
    const float* x      = (const float*)d_in[0];
    const float* conv_w = (const float*)d_in[1];
    const float* conv_b = (const float*)d_in[2];
    const float* gamma  = (const float*)d_in[3];
    const float* beta   = (const float*)d_in[4];
    float* y = (float*)d_out;

    cudaFuncSetAttribute(xj_kernel, cudaFuncAttributeMaxDynamicSharedMemorySize, XJ_SMEM);
    cudaFuncSetAttribute(gemm_kernel, cudaFuncAttributeMaxDynamicSharedMemorySize, GEMM_SMEM);

    wb_kernel<<<128, 256>>>(conv_w);            // 1
    xj_kernel<<<512, 1024, XJ_SMEM>>>(x);       // 2
    mid_marker_kernel<<<1, 32>>>();             // 3 (keeps gemm in ncu's slot)
    gemm_kernel<<<1024, 256, GEMM_SMEM>>>(conv_b, y);   // 4 <- profiled
    stats1_kernel<<<64, 256>>>();               // 5
    stats2_kernel<<<1, 128>>>(gamma, beta);     // 6
    bn_gelu_kernel<<<16384, 256>>>(y);          // 7
}